// round 13
// baseline (speedup 1.0000x reference)
#include <cuda_runtime.h>

#define NB 16
#define CI 4
#define CO 32
#define HH 400
#define RK 4
#define H4 100          // HH/4
#define KT 80           // k-tile in rowcol kernel
#define KT4 20          // KT/4

// ---- scratch (static device arrays: allocation-free) ----
__device__ float g_xt[NB*CI*HH*HH];     // X transposed per (n,c): [n][c][j][k]
__device__ float g_rows[NB*CO*HH];      // rows[n][o][i]
__device__ float g_cols[NB*CO*HH];      // cols[n][o][j]
__device__ float g_lt[HH*CO*CI*RK];     // weight re-layout: [j][o][c][r]

// ---- cp.async helpers ----
__device__ __forceinline__ void cp_async16(void* sdst, const void* gsrc) {
    unsigned s = (unsigned)__cvta_generic_to_shared(sdst);
    asm volatile("cp.async.cg.shared.global [%0], [%1], 16;" :: "r"(s), "l"(gsrc) : "memory");
}
#define CP_COMMIT() asm volatile("cp.async.commit_group;" ::: "memory")
#define CP_WAIT1()  asm volatile("cp.async.wait_group 1;"  ::: "memory")
#define CP_WAIT0()  asm volatile("cp.async.wait_group 0;"  ::: "memory")

// ============================================================
// Kernel 0a: 32x32 tiled transpose of each (n,c) 400x400 image
// ============================================================
__global__ void transpose_k(const float* __restrict__ x) {
    __shared__ float tile[32][33];
    int nc = blockIdx.z;
    int k0 = blockIdx.x * 32, j0 = blockIdx.y * 32;
    const float* src = x    + nc * (HH*HH);
    float*       dst = g_xt + nc * (HH*HH);
    int tx = threadIdx.x, ty = threadIdx.y;
    #pragma unroll
    for (int dy = 0; dy < 32; dy += 8) {
        int k = k0 + ty + dy, j = j0 + tx;
        if (k < HH && j < HH) tile[ty+dy][tx] = src[k*HH + j];
    }
    __syncthreads();
    #pragma unroll
    for (int dy = 0; dy < 32; dy += 8) {
        int j = j0 + ty + dy, k = k0 + tx;
        if (j < HH && k < HH) dst[j*HH + k] = tile[tx][ty+dy];
    }
}

// ============================================================
// Kernel 0b: weight re-layout  L[o,c,j,r] -> LT[j][o][c][r]
// ============================================================
__global__ void build_lt_k(const float* __restrict__ wl) {
    int idx = blockIdx.x * blockDim.x + threadIdx.x;
    if (idx >= CO*CI*HH*RK) return;
    int r = idx & 3;
    int t = idx >> 2;
    int j = t % HH; t /= HH;
    int c = t & 3;
    int o = t >> 2;
    g_lt[j*(CO*CI*RK) + o*(CI*RK) + c*RK + r] = wl[idx];
}

// ============================================================
// Kernel 1: rows & cols (R9/R12 pipelined version — measured good).
//   Ts[o][84]: float4 contract loads conflict-free. x-tiles cp.async
//   double-buffered so their L2 latency overlaps the Ts build.
// ============================================================
__global__ void __launch_bounds__(256) rowcol_k(const float* __restrict__ x,
                                                const float* __restrict__ wl) {
    int i = blockIdx.x;
    const float* xsrc = blockIdx.y ? g_xt  : x;
    float*       dst  = blockIdx.y ? g_cols : g_rows;

    __shared__ float4 Lis4[CI][CO];        // L[o,c,i,:]
    __shared__ float4 xs4[2][NB][KT4];     // x tiles, double-buffered
    __shared__ float  Ts[CO][84];          // T-slice [o][k], pad 84
    __shared__ float  red[4][CO][NB];

    int t = threadIdx.x;
    if (t < CO*CI) {
        int o = t >> 2, c = t & 3;
        Lis4[c][o] = *(const float4*)&wl[((o*CI + c)*HH + i)*RK];
    }

    int o  = t & 31;
    int g  = t >> 5;       // 0..7
    int nq = g & 1;        // n base = nq*8
    int kh = g >> 1;       // k quarter (20 k = 5 float4)

    float acc[8];
    #pragma unroll
    for (int u = 0; u < 8; u++) acc[u] = 0.f;

    // issue x-tile copy for stage s into buffer b;  stage s: c = s/5, kt = s%5
    #define ISSUE_XS(s, b)                                                        \
        do {                                                                      \
            int c_ = (s) / 5, kt_ = (s) - c_*5;                                   \
            for (int u = t; u < NB*KT4; u += 256) {                               \
                int n_ = u / KT4, q_ = u - n_*KT4;                                \
                cp_async16(&xs4[b][n_][q_],                                       \
                    &xsrc[((size_t)(n_*CI + c_)*HH + i)*HH + kt_*KT + q_*4]);     \
            }                                                                     \
        } while (0)

    ISSUE_XS(0, 0); CP_COMMIT();

    for (int s = 0; s < CI*(HH/KT); s++) {
        __syncthreads();   // prev contract done: Ts free, xs buf[(s+1)&1] free
        if (s + 1 < CI*(HH/KT)) { ISSUE_XS(s + 1, (s + 1) & 1); CP_COMMIT(); }

        // build Ts[o][k] for this stage
        {
            int c = s / 5, kt = s - (s/5)*5;
            #pragma unroll
            for (int u = 0; u < 10; u++) {
                int e  = t + u*256;
                int oo = e / KT, kk = e - oo*KT;
                float4 lv = *(const float4*)&wl[((oo*CI + c)*HH + kt*KT + kk)*RK];
                float4 li = Lis4[c][oo];
                Ts[oo][kk] = lv.x*li.x + lv.y*li.y + lv.z*li.z + lv.w*li.w;
            }
        }
        if (s + 1 < CI*(HH/KT)) CP_WAIT1(); else CP_WAIT0();   // stage s arrived
        __syncthreads();

        // contract: acc[n] += sum_k xs[n][k] * Ts[o][k]
        const float4* tsr = (const float4*)&Ts[o][0];   // o*336 B: 16B aligned
        const float4 (*xb)[KT4] = xs4[s & 1];
        #pragma unroll
        for (int q = 0; q < 5; q++) {
            float4 tv = tsr[kh*5 + q];
            #pragma unroll
            for (int nn = 0; nn < 8; nn++) {
                float4 xv = xb[nq*8 + nn][kh*5 + q];    // broadcast across lanes
                acc[nn] += xv.x*tv.x + xv.y*tv.y + xv.z*tv.z + xv.w*tv.w;
            }
        }
    }
    #undef ISSUE_XS

    // reduce over kh quarters
    #pragma unroll
    for (int nn = 0; nn < 8; nn++) red[kh][o][nq*8 + nn] = acc[nn];
    __syncthreads();
    for (int u = t; u < CO*NB; u += 256) {
        int o2 = u & 31, n2 = u >> 5;
        dst[(n2*CO + o2)*HH + i] =
            red[0][o2][n2] + red[1][o2][n2] + red[2][o2][n2] + red[3][o2][n2];
    }
}

// ============================================================
// Kernel 2: main elementwise kernel.
//   NOW: grid (HH, 4), 400 threads, 8 o's per block, 2 blocks/SM
//   (__launch_bounds__(400, 2): regs 2*400*~72 <= 64K, smem 2*100KB <= 227KB).
//   Two independent barrier domains per SM -> one block's staging phase
//   overlaps the other's compute/store phase. Inner loop identical to the
//   proven R6/R12 form: cols register-double-buffered, no in-loop barriers.
//   x-row staged via cp.async (no LDG->STS round-trip).
// ============================================================
__global__ void __launch_bounds__(400, 2) main_k(const float* __restrict__ x,
                                                 const float* __restrict__ wl,
                                                 const float* __restrict__ bias,
                                                 float* __restrict__ out) {
    extern __shared__ float4 sx4[];           // [NB*CI*H4] = 6400 float4 = 100 KB
    __shared__ float  rbs[NB*8];              // rows + bias for this block's 8 o's
    __shared__ float4 sLi[8*CI];              // L[o,c,i,:] for this block's 8 o's

    int t = threadIdx.x;
    int i = blockIdx.x;
    int obase = blockIdx.y * 8;

    // stage x-row for all (n,c) via cp.async (16 ops/thread, full MLP)
    for (int u = t; u < NB*CI*H4; u += 400) {
        int n   = u / (CI*H4);
        int rem = u - n*(CI*H4);
        int c   = rem / H4;
        int q   = rem - c*H4;
        cp_async16(&sx4[u], &x[((size_t)(n*CI + c)*HH + i)*HH + q*4]);
    }
    CP_COMMIT();

    if (t < NB*8) {
        int n = t >> 3, oL = t & 7;
        rbs[t] = g_rows[(n*CO + obase + oL)*HH + i] + bias[obase + oL];
    }
    if (t < 8*CI) {
        int oL = t >> 2, c = t & 3;
        sLi[t] = *(const float4*)&wl[(((obase + oL)*CI + c)*HH + i)*RK];
    }

    int og = t / 100;          // 0..3 -> 2 o's each (8 o's total)
    int jg = t - og * 100;     // 0..99
    int oL0 = og * 2;
    int o0  = obase + oL0;

    // G4[oo][c] = { dot(L[o,c,i,:], L[o,c,jg*4+jj,:]) : jj=0..3 }
    // (g_lt reads don't depend on smem; issue before the barrier)
    float4 G4[2][4];
    CP_WAIT0();
    __syncthreads();

    #pragma unroll
    for (int oo = 0; oo < 2; oo++) {
        int oL = oL0 + oo;
        #pragma unroll
        for (int c = 0; c < 4; c++) {
            float4 li = sLi[oL*4 + c];
            const float* ltb = &g_lt[(size_t)(jg*4)*(CO*CI*RK) + (obase + oL)*(CI*RK) + c*RK];
            float4 l0 = *(const float4*)(ltb + 0*(CO*CI*RK));
            float4 l1 = *(const float4*)(ltb + 1*(CO*CI*RK));
            float4 l2 = *(const float4*)(ltb + 2*(CO*CI*RK));
            float4 l3 = *(const float4*)(ltb + 3*(CO*CI*RK));
            G4[oo][c].x = li.x*l0.x + li.y*l0.y + li.z*l0.z + li.w*l0.w;
            G4[oo][c].y = li.x*l1.x + li.y*l1.y + li.z*l1.z + li.w*l1.w;
            G4[oo][c].z = li.x*l2.x + li.y*l2.y + li.z*l2.z + li.w*l2.w;
            G4[oo][c].w = li.x*l3.x + li.y*l3.y + li.z*l3.z + li.w*l3.w;
        }
    }

    // cols pointers for the two o's of this thread
    const float* cp0 = &g_cols[(size_t)(o0    )*HH + jg*4];
    const float* cp1 = &g_cols[(size_t)(o0 + 1)*HH + jg*4];

    // prefetch n=0
    float4 cva0 = *(const float4*)cp0;
    float4 cva1 = *(const float4*)cp1;

    for (int n = 0; n < NB; n++) {
        // prefetch next n's cols (clamped at the end; redundant load is harmless)
        int np = (n < NB-1) ? n+1 : n;
        float4 cvb0 = *(const float4*)(cp0 + (size_t)np*CO*HH);
        float4 cvb1 = *(const float4*)(cp1 + (size_t)np*CO*HH);

        float4 xv0 = sx4[(n*CI + 0)*H4 + jg];
        float4 xv1 = sx4[(n*CI + 1)*H4 + jg];
        float4 xv2 = sx4[(n*CI + 2)*H4 + jg];
        float4 xv3 = sx4[(n*CI + 3)*H4 + jg];

        #pragma unroll
        for (int oo = 0; oo < 2; oo++) {
            float4 cv = oo ? cva1 : cva0;
            float rb  = rbs[n*8 + oL0 + oo];
            float4 res;
            res.x = rb + cv.x - (xv0.x*G4[oo][0].x + xv1.x*G4[oo][1].x + xv2.x*G4[oo][2].x + xv3.x*G4[oo][3].x);
            res.y = rb + cv.y - (xv0.y*G4[oo][0].y + xv1.y*G4[oo][1].y + xv2.y*G4[oo][2].y + xv3.y*G4[oo][3].y);
            res.z = rb + cv.z - (xv0.z*G4[oo][0].z + xv1.z*G4[oo][1].z + xv2.z*G4[oo][2].z + xv3.z*G4[oo][3].z);
            res.w = rb + cv.w - (xv0.w*G4[oo][0].w + xv1.w*G4[oo][1].w + xv2.w*G4[oo][2].w + xv3.w*G4[oo][3].w);
            *(float4*)&out[((size_t)(n*CO + o0 + oo)*HH + i)*HH + jg*4] = res;
        }
        cva0 = cvb0;
        cva1 = cvb1;
    }
}

// ============================================================
extern "C" void kernel_launch(void* const* d_in, const int* in_sizes, int n_in,
                              void* d_out, int out_size) {
    // defensive input mapping by element count
    const float* x    = (const float*)d_in[0];
    const float* wl   = (const float*)d_in[1];
    const float* bias = (const float*)d_in[2];
    for (int k = 0; k < n_in; k++) {
        if (in_sizes[k] == NB*CI*HH*HH) x    = (const float*)d_in[k];
        else if (in_sizes[k] == CO*CI*HH*RK) wl = (const float*)d_in[k];
        else if (in_sizes[k] == CO)      bias = (const float*)d_in[k];
    }
    float* out = (float*)d_out;

    int dyn_bytes = NB*CI*H4 * (int)sizeof(float4);   // 100 KB
    cudaFuncSetAttribute(main_k, cudaFuncAttributeMaxDynamicSharedMemorySize,
                         dyn_bytes);

    transpose_k<<<dim3((HH+31)/32, (HH+31)/32, NB*CI), dim3(32, 8)>>>(x);
    build_lt_k<<<(CO*CI*HH*RK + 255)/256, 256>>>(wl);
    rowcol_k<<<dim3(HH, 2), 256>>>(x, wl);
    main_k<<<dim3(HH, 4), 400, dyn_bytes>>>(x, wl, bias, out);
}

// round 15
// speedup vs baseline: 1.1317x; 1.1317x over previous
#include <cuda_runtime.h>

#define NB 16
#define CI 4
#define CO 32
#define HH 400
#define RK 4
#define H4 100          // HH/4
#define KT 80           // k-tile in rowcol kernel
#define KT4 20          // KT/4

// ---- scratch (static device arrays: allocation-free) ----
__device__ float g_xt[NB*CI*HH*HH];     // X transposed per (n,c): [n][c][j][k]
__device__ float g_rows[NB*CO*HH];      // rows[n][o][i]
__device__ float g_cols[NB*CO*HH];      // cols[n][o][j]
__device__ float g_lt[HH*CO*CI*RK];     // weight re-layout: [j][o][c][r]

// ---- cp.async helpers ----
__device__ __forceinline__ void cp_async16(void* sdst, const void* gsrc) {
    unsigned s = (unsigned)__cvta_generic_to_shared(sdst);
    asm volatile("cp.async.cg.shared.global [%0], [%1], 16;" :: "r"(s), "l"(gsrc) : "memory");
}
#define CP_COMMIT() asm volatile("cp.async.commit_group;" ::: "memory")
#define CP_WAIT1()  asm volatile("cp.async.wait_group 1;"  ::: "memory")
#define CP_WAIT0()  asm volatile("cp.async.wait_group 0;"  ::: "memory")

// evict-first streaming store (inline PTX; intrinsic __stcs suspected in
// R10/R11 container failures, so we use raw asm)
__device__ __forceinline__ void stg_cs128(float* gptr, float4 v) {
    asm volatile("st.global.cs.v4.f32 [%0], {%1, %2, %3, %4};"
                 :: "l"(gptr), "f"(v.x), "f"(v.y), "f"(v.z), "f"(v.w) : "memory");
}

// ============================================================
// Kernel 0a: 32x32 tiled transpose of each (n,c) 400x400 image
// ============================================================
__global__ void transpose_k(const float* __restrict__ x) {
    __shared__ float tile[32][33];
    int nc = blockIdx.z;
    int k0 = blockIdx.x * 32, j0 = blockIdx.y * 32;
    const float* src = x    + nc * (HH*HH);
    float*       dst = g_xt + nc * (HH*HH);
    int tx = threadIdx.x, ty = threadIdx.y;
    #pragma unroll
    for (int dy = 0; dy < 32; dy += 8) {
        int k = k0 + ty + dy, j = j0 + tx;
        if (k < HH && j < HH) tile[ty+dy][tx] = src[k*HH + j];
    }
    __syncthreads();
    #pragma unroll
    for (int dy = 0; dy < 32; dy += 8) {
        int j = j0 + ty + dy, k = k0 + tx;
        if (j < HH && k < HH) dst[j*HH + k] = tile[tx][ty+dy];
    }
}

// ============================================================
// Kernel 0b: weight re-layout  L[o,c,j,r] -> LT[j][o][c][r]
// ============================================================
__global__ void build_lt_k(const float* __restrict__ wl) {
    int idx = blockIdx.x * blockDim.x + threadIdx.x;
    if (idx >= CO*CI*HH*RK) return;
    int r = idx & 3;
    int t = idx >> 2;
    int j = t % HH; t /= HH;
    int c = t & 3;
    int o = t >> 2;
    g_lt[j*(CO*CI*RK) + o*(CI*RK) + c*RK + r] = wl[idx];
}

// ============================================================
// Kernel 1: rows & cols (R9/R12 pipelined version — measured good).
//   Ts[o][84]: float4 contract loads conflict-free. x-tiles cp.async
//   double-buffered so their L2 latency overlaps the Ts build.
// ============================================================
__global__ void __launch_bounds__(256) rowcol_k(const float* __restrict__ x,
                                                const float* __restrict__ wl) {
    int i = blockIdx.x;
    const float* xsrc = blockIdx.y ? g_xt  : x;
    float*       dst  = blockIdx.y ? g_cols : g_rows;

    __shared__ float4 Lis4[CI][CO];        // L[o,c,i,:]
    __shared__ float4 xs4[2][NB][KT4];     // x tiles, double-buffered
    __shared__ float  Ts[CO][84];          // T-slice [o][k], pad 84
    __shared__ float  red[4][CO][NB];

    int t = threadIdx.x;
    if (t < CO*CI) {
        int o = t >> 2, c = t & 3;
        Lis4[c][o] = *(const float4*)&wl[((o*CI + c)*HH + i)*RK];
    }

    int o  = t & 31;
    int g  = t >> 5;       // 0..7
    int nq = g & 1;        // n base = nq*8
    int kh = g >> 1;       // k quarter (20 k = 5 float4)

    float acc[8];
    #pragma unroll
    for (int u = 0; u < 8; u++) acc[u] = 0.f;

    // issue x-tile copy for stage s into buffer b;  stage s: c = s/5, kt = s%5
    #define ISSUE_XS(s, b)                                                        \
        do {                                                                      \
            int c_ = (s) / 5, kt_ = (s) - c_*5;                                   \
            for (int u = t; u < NB*KT4; u += 256) {                               \
                int n_ = u / KT4, q_ = u - n_*KT4;                                \
                cp_async16(&xs4[b][n_][q_],                                       \
                    &xsrc[((size_t)(n_*CI + c_)*HH + i)*HH + kt_*KT + q_*4]);     \
            }                                                                     \
        } while (0)

    ISSUE_XS(0, 0); CP_COMMIT();

    for (int s = 0; s < CI*(HH/KT); s++) {
        __syncthreads();   // prev contract done: Ts free, xs buf[(s+1)&1] free
        if (s + 1 < CI*(HH/KT)) { ISSUE_XS(s + 1, (s + 1) & 1); CP_COMMIT(); }

        // build Ts[o][k] for this stage
        {
            int c = s / 5, kt = s - (s/5)*5;
            #pragma unroll
            for (int u = 0; u < 10; u++) {
                int e  = t + u*256;
                int oo = e / KT, kk = e - oo*KT;
                float4 lv = *(const float4*)&wl[((oo*CI + c)*HH + kt*KT + kk)*RK];
                float4 li = Lis4[c][oo];
                Ts[oo][kk] = lv.x*li.x + lv.y*li.y + lv.z*li.z + lv.w*li.w;
            }
        }
        if (s + 1 < CI*(HH/KT)) CP_WAIT1(); else CP_WAIT0();   // stage s arrived
        __syncthreads();

        // contract: acc[n] += sum_k xs[n][k] * Ts[o][k]
        const float4* tsr = (const float4*)&Ts[o][0];   // o*336 B: 16B aligned
        const float4 (*xb)[KT4] = xs4[s & 1];
        #pragma unroll
        for (int q = 0; q < 5; q++) {
            float4 tv = tsr[kh*5 + q];
            #pragma unroll
            for (int nn = 0; nn < 8; nn++) {
                float4 xv = xb[nq*8 + nn][kh*5 + q];    // broadcast across lanes
                acc[nn] += xv.x*tv.x + xv.y*tv.y + xv.z*tv.z + xv.w*tv.w;
            }
        }
    }
    #undef ISSUE_XS

    // reduce over kh quarters
    #pragma unroll
    for (int nn = 0; nn < 8; nn++) red[kh][o][nq*8 + nn] = acc[nn];
    __syncthreads();
    for (int u = t; u < CO*NB; u += 256) {
        int o2 = u & 31, n2 = u >> 5;
        dst[(n2*CO + o2)*HH + i] =
            red[0][o2][n2] + red[1][o2][n2] + red[2][o2][n2] + red[3][o2][n2];
    }
}

// ============================================================
// Kernel 2: main elementwise kernel (exact R12 form — measured 190us —
//   with ONE delta: out stores via st.global.cs to stop the 327MB write
//   stream from evicting the cols/x/lt reuse set out of L2).
//   grid (HH, 2): block = (i, o-half of 16). 800 threads:
//   jg = t%100, og = t/100 -> 2 o's each, single pass. x-row staged in
//   smem; cols register-double-buffered across the n-loop (no barriers).
// ============================================================
__global__ void __launch_bounds__(800, 1) main_k(const float* __restrict__ x,
                                                 const float* __restrict__ wl,
                                                 const float* __restrict__ bias,
                                                 float* __restrict__ out) {
    extern __shared__ float4 sx4[];           // [NB*CI*H4] = 6400 float4 = 100 KB
    __shared__ float  rbs[NB*16];             // rows + bias for this block's 16 o's
    __shared__ float4 sLi[16*CI];             // L[o,c,i,:] for this block's 16 o's

    int t = threadIdx.x;
    int i = blockIdx.x;
    int obase = blockIdx.y * 16;

    for (int u = t; u < NB*CI*H4; u += 800) {
        int n   = u / (CI*H4);
        int rem = u - n*(CI*H4);
        int c   = rem / H4;
        int q   = rem - c*H4;
        sx4[u] = *(const float4*)&x[((n*CI + c)*HH + i)*HH + q*4];
    }
    if (t < NB*16) {
        int n = t >> 4, oL = t & 15;
        rbs[t] = g_rows[(n*CO + obase + oL)*HH + i] + bias[obase + oL];
    }
    if (t < 16*CI) {
        int oL = t >> 2, c = t & 3;
        sLi[t] = *(const float4*)&wl[(((obase + oL)*CI + c)*HH + i)*RK];
    }
    __syncthreads();

    int og = t / 100;          // 0..7 -> 2 o's each
    int jg = t - og * 100;     // 0..99
    int oL0 = og * 2;
    int o0  = obase + oL0;

    // G4[oo][c] = { dot(L[o,c,i,:], L[o,c,jg*4+jj,:]) : jj=0..3 }
    float4 G4[2][4];
    #pragma unroll
    for (int oo = 0; oo < 2; oo++) {
        int oL = oL0 + oo;
        #pragma unroll
        for (int c = 0; c < 4; c++) {
            float4 li = sLi[oL*4 + c];
            const float* ltb = &g_lt[(size_t)(jg*4)*(CO*CI*RK) + (obase + oL)*(CI*RK) + c*RK];
            float4 l0 = *(const float4*)(ltb + 0*(CO*CI*RK));
            float4 l1 = *(const float4*)(ltb + 1*(CO*CI*RK));
            float4 l2 = *(const float4*)(ltb + 2*(CO*CI*RK));
            float4 l3 = *(const float4*)(ltb + 3*(CO*CI*RK));
            G4[oo][c].x = li.x*l0.x + li.y*l0.y + li.z*l0.z + li.w*l0.w;
            G4[oo][c].y = li.x*l1.x + li.y*l1.y + li.z*l1.z + li.w*l1.w;
            G4[oo][c].z = li.x*l2.x + li.y*l2.y + li.z*l2.z + li.w*l2.w;
            G4[oo][c].w = li.x*l3.x + li.y*l3.y + li.z*l3.z + li.w*l3.w;
        }
    }

    // cols pointers for the two o's of this thread
    const float* cp0 = &g_cols[(size_t)(o0    )*HH + jg*4];
    const float* cp1 = &g_cols[(size_t)(o0 + 1)*HH + jg*4];

    // prefetch n=0
    float4 cva0 = *(const float4*)cp0;
    float4 cva1 = *(const float4*)cp1;

    for (int n = 0; n < NB; n++) {
        // prefetch next n's cols (clamped at the end; redundant load is harmless)
        int np = (n < NB-1) ? n+1 : n;
        float4 cvb0 = *(const float4*)(cp0 + (size_t)np*CO*HH);
        float4 cvb1 = *(const float4*)(cp1 + (size_t)np*CO*HH);

        float4 xv0 = sx4[(n*CI + 0)*H4 + jg];
        float4 xv1 = sx4[(n*CI + 1)*H4 + jg];
        float4 xv2 = sx4[(n*CI + 2)*H4 + jg];
        float4 xv3 = sx4[(n*CI + 3)*H4 + jg];

        #pragma unroll
        for (int oo = 0; oo < 2; oo++) {
            float4 cv = oo ? cva1 : cva0;
            float rb  = rbs[n*16 + oL0 + oo];
            float4 res;
            res.x = rb + cv.x - (xv0.x*G4[oo][0].x + xv1.x*G4[oo][1].x + xv2.x*G4[oo][2].x + xv3.x*G4[oo][3].x);
            res.y = rb + cv.y - (xv0.y*G4[oo][0].y + xv1.y*G4[oo][1].y + xv2.y*G4[oo][2].y + xv3.y*G4[oo][3].y);
            res.z = rb + cv.z - (xv0.z*G4[oo][0].z + xv1.z*G4[oo][1].z + xv2.z*G4[oo][2].z + xv3.z*G4[oo][3].z);
            res.w = rb + cv.w - (xv0.w*G4[oo][0].w + xv1.w*G4[oo][1].w + xv2.w*G4[oo][2].w + xv3.w*G4[oo][3].w);
            stg_cs128(&out[((size_t)(n*CO + o0 + oo)*HH + i)*HH + jg*4], res);
        }
        cva0 = cvb0;
        cva1 = cvb1;
    }
}

// ============================================================
extern "C" void kernel_launch(void* const* d_in, const int* in_sizes, int n_in,
                              void* d_out, int out_size) {
    // defensive input mapping by element count
    const float* x    = (const float*)d_in[0];
    const float* wl   = (const float*)d_in[1];
    const float* bias = (const float*)d_in[2];
    for (int k = 0; k < n_in; k++) {
        if (in_sizes[k] == NB*CI*HH*HH) x    = (const float*)d_in[k];
        else if (in_sizes[k] == CO*CI*HH*RK) wl = (const float*)d_in[k];
        else if (in_sizes[k] == CO)      bias = (const float*)d_in[k];
    }
    float* out = (float*)d_out;

    int dyn_bytes = NB*CI*H4 * (int)sizeof(float4);   // 100 KB
    cudaFuncSetAttribute(main_k, cudaFuncAttributeMaxDynamicSharedMemorySize,
                         dyn_bytes);

    transpose_k<<<dim3((HH+31)/32, (HH+31)/32, NB*CI), dim3(32, 8)>>>(x);
    build_lt_k<<<(CO*CI*HH*RK + 255)/256, 256>>>(wl);
    rowcol_k<<<dim3(HH, 2), 256>>>(x, wl);
    main_k<<<dim3(HH, 2), 800, dyn_bytes>>>(x, wl, bias, out);
}